// round 17
// baseline (speedup 1.0000x reference)
#include <cuda_runtime.h>
#include <cstdint>

#define B_ 8
#define M_ 2048
#define N_ 2048
#define R_ 32

#define L1C 10.24f
#define L2C 10.24f
#define EPSC 1e-16f

#define KT 64
#define NCH (N_ / KT)            // 32 chunks
#define AST 72                   // A tile stride (halfwords): 64 + 8 pad
#define BST 40                   // B tile stride: 32 + 8 pad
#define A_BYTES (64 * AST * 2)   // 9216
#define B_BYTES (64 * BST * 2)   // 5120
#define OFF_ALO A_BYTES
#define OFF_BHI (2 * A_BYTES)
#define OFF_BLO (2 * A_BYTES + B_BYTES)
#define BUF (2 * A_BYTES + 2 * B_BYTES)   // 28672
#define SMEM_DYN (2 * BUF)                // 57344 (res[4][64][33]=33792 fits)

#define GP 32                    // gram split count
#define GCHUNK 64

// Scratch (device globals; no allocation allowed)
__device__ float g_bp[GP * B_ * R_ * R_];  // gram partials

// ---- helpers -------------------------------------------------------------
__device__ __forceinline__ uint32_t pack2bf(float lo, float hi) {   // mem order [lo,hi]
    uint32_t r; asm("cvt.rn.bf16x2.f32 %0, %1, %2;" : "=r"(r) : "f"(hi), "f"(lo)); return r;
}
__device__ __forceinline__ void cvt_hilo(float4 xv, uint2& hi, uint2& lo) {
    uint32_t h01 = pack2bf(xv.x, xv.y);
    uint32_t h23 = pack2bf(xv.z, xv.w);
    float hx = __uint_as_float(h01 << 16), hy = __uint_as_float(h01 & 0xFFFF0000u);
    float hz = __uint_as_float(h23 << 16), hw = __uint_as_float(h23 & 0xFFFF0000u);
    uint32_t l01 = pack2bf(xv.x - hx, xv.y - hy);
    uint32_t l23 = pack2bf(xv.z - hz, xv.w - hw);
    hi = make_uint2(h01, h23); lo = make_uint2(l01, l23);
}
__device__ __forceinline__ uint32_t s2u(const void* p) {
    uint32_t a;
    asm("{ .reg .u64 t; cvta.to.shared.u64 t, %1; cvt.u32.u64 %0, t; }" : "=r"(a) : "l"(p));
    return a;
}
__device__ __forceinline__ void ldsm4(uint32_t* r, uint32_t addr) {
    asm volatile("ldmatrix.sync.aligned.m8n8.x4.shared.b16 {%0,%1,%2,%3}, [%4];"
                 : "=r"(r[0]), "=r"(r[1]), "=r"(r[2]), "=r"(r[3]) : "r"(addr));
}
__device__ __forceinline__ void ldsm4t(uint32_t* r, uint32_t addr) {
    asm volatile("ldmatrix.sync.aligned.m8n8.x4.trans.shared.b16 {%0,%1,%2,%3}, [%4];"
                 : "=r"(r[0]), "=r"(r[1]), "=r"(r[2]), "=r"(r[3]) : "r"(addr));
}
__device__ __forceinline__ void mma16816(float* c, const uint32_t* a, uint32_t b0, uint32_t b1) {
    asm volatile(
        "mma.sync.aligned.m16n8k16.row.col.f32.bf16.bf16.f32 "
        "{%0,%1,%2,%3}, {%4,%5,%6,%7}, {%8,%9}, {%0,%1,%2,%3};"
        : "+f"(c[0]), "+f"(c[1]), "+f"(c[2]), "+f"(c[3])
        : "r"(a[0]), "r"(a[1]), "r"(a[2]), "r"(a[3]), "r"(b0), "r"(b1));
}

// ======================= gram partial kernel =======================
// grid (GP, B_) = 256 CTAs, 256 threads; 64-row slices for 2x parallelism.
__global__ void gram_partial_kernel(const float* __restrict__ vin) {
    __shared__ float vs[GCHUNK][R_];
    int b = blockIdx.y, p = blockIdx.x, tid = threadIdx.x;
    const float4* src = (const float4*)(vin + ((size_t)b * N_ + p * GCHUNK) * R_);
    float4* dst = (float4*)&vs[0][0];
#pragma unroll
    for (int i = 0; i < 2; i++) dst[tid + 256 * i] = src[tid + 256 * i];
    __syncthreads();
    int r = tid >> 3, s4 = (tid & 7) * 4;
    float ax = 0.f, ay = 0.f, az = 0.f, aw = 0.f;
#pragma unroll 8
    for (int m = 0; m < GCHUNK; m++) {
        float vr = vs[m][r];
        float4 sv = *(const float4*)&vs[m][s4];
        ax += vr * sv.x; ay += vr * sv.y; az += vr * sv.z; aw += vr * sv.w;
    }
    float* o = g_bp + ((size_t)p * B_ + b) * (R_ * R_) + r * R_ + s4;
    o[0] = ax; o[1] = ay; o[2] = az; o[3] = aw;
}

// ======================= fused GEMM + CD kernel =======================
// TRANSA=false: rows = m, A = x[m][k] natural, normal ldmatrix.
// TRANSA=true:  rows = n, A = x[k][n] natural, ldmatrix.trans.
// B = v/u natural [k][r], fragments via ldmatrix.trans.
// 8 warps = 2 row-groups (32 rows) x 4 k-quarters (16 k).
// NO register prefetch; latency hidden by 3 CTAs/SM (24 warps).
// grid (M_/64, B_) = 256 CTAs.
template <bool TRANSA>
__global__ void __launch_bounds__(256, 3)
fused_gemm_cd_kernel(const float* __restrict__ x, const float* __restrict__ w,
                     const float* __restrict__ uin, float* __restrict__ uout) {
    extern __shared__ char smc[];
    __shared__ float bs[R_][R_];
    __shared__ float inv[R_];

    int tid = threadIdx.x, wid = tid >> 5, lane = tid & 31;
    int g = lane >> 2, t4 = lane & 3;
    int wrow = (wid & 1) * 32;      // row-group base
    int kq   = wid >> 1;            // k-quarter 0..3
    int b = blockIdx.y, m0 = blockIdx.x * 64;

    // in-kernel gram reduce (fixed order -> deterministic)
    {
        const float4* bp4 = (const float4*)g_bp;
        float4 s = {0.f, 0.f, 0.f, 0.f};
#pragma unroll
        for (int p = 0; p < GP; p++) {
            float4 t = bp4[((size_t)p * B_ + b) * 256 + tid];
            s.x += t.x; s.y += t.y; s.z += t.z; s.w += t.w;
        }
        ((float4*)&bs[0][0])[tid] = s;
    }
    __syncthreads();
    if (tid < R_) inv[tid] = 1.0f / (bs[tid][tid] + L2C + EPSC);
    // inv visibility to the epilogue ordered by the loop's syncs.

    const float* xb = x + (size_t)b * M_ * N_;
    const float* wb = w + (size_t)b * N_ * R_;

    int arow = tid >> 2;     // 0..63 (A staging row)
    int ac   = tid & 3;      // f4 col base, +4*i

    // lane fragment offsets (halfword units); k16 = kq*16 folded in
    int k16 = kq * 16;
    int aoff0, aoff1, boff;
    if (TRANSA) {
        int kr = k16 + (lane >> 4) * 8 + (lane & 7);        // source row = k
        int nb = wrow + (((lane >> 3) & 1) * 8);            // n base
        aoff0 = kr * AST + nb;
        aoff1 = kr * AST + nb + 16;
    } else {
        int rb = wrow + (((lane >> 3) & 1) * 8) + (lane & 7);
        aoff0 = rb * AST + (lane >> 4) * 8 + k16;
        aoff1 = (rb + 16) * AST + (lane >> 4) * 8 + k16;
    }
    boff = (k16 + (((lane >> 3) & 1) * 8) + (lane & 7)) * BST + (lane >> 4) * 8;

    float acc[2][4][4] = {};

    for (int t = 0; t < NCH; t++) {
        char* buf = smc + (t & 1) * BUF;
        uint16_t* Ahi = (uint16_t*)buf;
        uint16_t* Alo = (uint16_t*)(buf + OFF_ALO);
        uint16_t* Bhi = (uint16_t*)(buf + OFF_BHI);
        uint16_t* Blo = (uint16_t*)(buf + OFF_BLO);

        // stage A inline: LDG -> cvt -> STS (natural layout, bf16 hi/lo)
#pragma unroll
        for (int i = 0; i < 4; i++) {
            int c4 = ac + 4 * i;
            float4 xv = TRANSA
                ? *(const float4*)(xb + (size_t)(t * KT + arow) * N_ + m0 + c4 * 4)
                : *(const float4*)(xb + (size_t)(m0 + arow) * N_ + t * KT + c4 * 4);
            uint2 hi, lo;
            cvt_hilo(xv, hi, lo);
            *(uint2*)&Ahi[arow * AST + c4 * 4] = hi;
            *(uint2*)&Alo[arow * AST + c4 * 4] = lo;
        }
        // stage B inline (natural [k][r]; w is L2-resident)
#pragma unroll
        for (int i = 0; i < 2; i++) {
            int idx = tid + 256 * i;
            int k = idx >> 3, r = (idx & 7) * 4;
            float4 pbv = *(const float4*)(wb + (size_t)(t * KT + k) * R_ + r);
            uint2 hi, lo;
            cvt_hilo(pbv, hi, lo);
            *(uint2*)&Bhi[k * BST + r] = hi;
            *(uint2*)&Blo[k * BST + r] = lo;
        }
        __syncthreads();

        uint32_t aAhi = s2u(Ahi), aAlo = s2u(Alo), aBhi = s2u(Bhi), aBlo = s2u(Blo);
        uint32_t bh[8], bl[8];
        ldsm4t(bh,     aBhi + 2 * boff);
        ldsm4t(bh + 4, aBhi + 2 * (boff + 16));
        ldsm4t(bl,     aBlo + 2 * boff);
        ldsm4t(bl + 4, aBlo + 2 * (boff + 16));
#pragma unroll
        for (int rt = 0; rt < 2; rt++) {
            int ao = (rt == 0) ? aoff0 : aoff1;
            uint32_t ah[4], al[4];
            if (TRANSA) { ldsm4t(ah, aAhi + 2 * ao); ldsm4t(al, aAlo + 2 * ao); }
            else        { ldsm4 (ah, aAhi + 2 * ao); ldsm4 (al, aAlo + 2 * ao); }
#pragma unroll
            for (int j = 0; j < 4; j++) {
                mma16816(acc[rt][j], ah, bh[2 * j], bh[2 * j + 1]);   // hi*hi
                mma16816(acc[rt][j], ah, bl[2 * j], bl[2 * j + 1]);   // hi*lo
                mma16816(acc[rt][j], al, bh[2 * j], bh[2 * j + 1]);   // lo*hi
            }
        }
        // no trailing sync: ping-pong; buffer reuse at t+2 guarded by sync in t+1.
    }

    // ======== fused epilogue: 4-plane k-split reduction + per-row CD ========
    __syncthreads();                 // all ldsm reads done before res overwrites bufs
    float* res = (float*)smc;        // [4 planes][64][33]
    {
        float* rp = res + kq * (64 * 33);
#pragma unroll
        for (int rt = 0; rt < 2; rt++) {
#pragma unroll
            for (int j = 0; j < 4; j++) {
                int row0 = wrow + rt * 16 + g;
                int c = j * 8 + t4 * 2;
                rp[row0 * 33 + c]           = acc[rt][j][0];
                rp[row0 * 33 + c + 1]       = acc[rt][j][1];
                rp[(row0 + 8) * 33 + c]     = acc[rt][j][2];
                rp[(row0 + 8) * 33 + c + 1] = acc[rt][j][3];
            }
        }
    }
    __syncthreads();

    if (tid < 64) {
        const float* ur = uin + ((size_t)b * M_ + m0 + tid) * R_;
        const float* r0 = res + tid * 33;
        float areg[R_], ureg[R_];
#pragma unroll
        for (int r = 0; r < R_; r++)
            areg[r] = (r0[r] + r0[64 * 33 + r]) + (r0[2 * 64 * 33 + r] + r0[3 * 64 * 33 + r]);
#pragma unroll
        for (int i = 0; i < 8; i++) {
            float4 t2 = *(const float4*)(ur + i * 4);
            ureg[4 * i + 0] = t2.x; ureg[4 * i + 1] = t2.y;
            ureg[4 * i + 2] = t2.z; ureg[4 * i + 3] = t2.w;
        }
#pragma unroll
        for (int r = 0; r < R_; r++) {
            float brr = bs[r][r];
            float d0 = 0.f, d1 = 0.f, d2 = 0.f, d3 = 0.f;
#pragma unroll
            for (int k = 0; k < R_; k += 4) {
                d0 += ureg[k + 0] * bs[k + 0][r];
                d1 += ureg[k + 1] * bs[k + 1][r];
                d2 += ureg[k + 2] * bs[k + 2][r];
                d3 += ureg[k + 3] * bs[k + 3][r];
            }
            float dot = (d0 + d1) + (d2 + d3);
            float z = areg[r] - (dot - ureg[r] * brr);
            float num = (z > L1C) ? (z - L1C) : ((z < -L1C) ? (z + L1C) : 0.0f);
            ureg[r] = (num + EPSC) * inv[r];
        }
        float* outr = uout + ((size_t)b * M_ + m0 + tid) * R_;
#pragma unroll
        for (int i = 0; i < 8; i++) {
            float4 o = {ureg[4 * i + 0], ureg[4 * i + 1], ureg[4 * i + 2], ureg[4 * i + 3]};
            *(float4*)(outr + i * 4) = o;
        }
    }
}

// ---------------------------------------------------------------------------
extern "C" void kernel_launch(void* const* d_in, const int* in_sizes, int n_in,
                              void* d_out, int out_size) {
    const float* x = (const float*)d_in[0];
    const float* u = (const float*)d_in[1];
    const float* v = (const float*)d_in[2];
    float* uout = (float*)d_out;
    float* vout = uout + (size_t)B_ * M_ * R_;

    cudaFuncSetAttribute(fused_gemm_cd_kernel<false>,
                         cudaFuncAttributeMaxDynamicSharedMemorySize, SMEM_DYN);
    cudaFuncSetAttribute(fused_gemm_cd_kernel<true>,
                         cudaFuncAttributeMaxDynamicSharedMemorySize, SMEM_DYN);

    dim3 gg(GP, B_);         // 32 x 8 = 256 CTAs
    dim3 gt(M_ / 64, B_);    // 32 x 8 = 256 CTAs

    // Phase 1: u update (gram of v; fused GEMM + reduce + CD)
    gram_partial_kernel<<<gg, 256>>>(v);
    fused_gemm_cd_kernel<false><<<gt, 256, SMEM_DYN>>>(x, v, u, uout);

    // Phase 2: v update (gram of new u; fused x^T GEMM via ldmatrix.trans + CD)
    gram_partial_kernel<<<gg, 256>>>(uout);
    fused_gemm_cd_kernel<true><<<gt, 256, SMEM_DYN>>>(x, uout, v, vout);
}